// round 11
// baseline (speedup 1.0000x reference)
#include <cuda_runtime.h>
#include <math.h>
#include <stdint.h>

#define T_STEPS 2048
#define BATCH   32
#define HID     256
#define ZCOLS   1024            // 4*HID, gate order f,i,o,c
#define MROWS   (T_STEPS * BATCH)
#define CLUSTER 8
#define REC_CTAS 128            // 16 clusters x 8 CTAs
#define REC_THREADS 256

// ---------------- scratch (device globals: no allocations allowed) ----------
__device__ float g_Zx[(size_t)MROWS * ZCOLS];   // row-major: Zx[t*32+b][col]

// ============================================================================
// Kernel 1: Zx[t*32+b][g*256+j] = sum_k x[b][t][k] * Wg[k][j] + bg[j]
// 128x128 tile SGEMM, BK=16, 256 threads, 8x8 microtile. (at fp32 roofline)
// ============================================================================
__global__ __launch_bounds__(256, 2)
void gemm_zx(const float* __restrict__ x,
             const float* __restrict__ Wf, const float* __restrict__ bf,
             const float* __restrict__ Wi, const float* __restrict__ bi,
             const float* __restrict__ Wo, const float* __restrict__ bo,
             const float* __restrict__ Wc, const float* __restrict__ bc)
{
    __shared__ float As[16 * 128];   // [k][m]
    __shared__ float Bs[16 * 128];   // [k][n]

    const int t = threadIdx.x;

    const float* Wg[4] = {Wf, Wi, Wo, Wc};
    const float* bg[4] = {bf, bi, bo, bc};

    const int N0 = blockIdx.x * 128;          // never straddles a gate
    const int gate = N0 >> 8;
    const int jb = N0 & 255;
    const float* __restrict__ W = Wg[gate];

    const int M0 = blockIdx.y * 128;
    const int tx = t & 15;
    const int ty = t >> 4;

    float acc[8][8];
    #pragma unroll
    for (int i = 0; i < 8; i++)
        #pragma unroll
        for (int j = 0; j < 8; j++) acc[i][j] = 0.f;

    for (int k0 = 0; k0 < 256; k0 += 16) {
        #pragma unroll
        for (int i = 0; i < 2; i++) {
            int f = t + i * 256;
            int kq  = f >> 7;
            int row = f & 127;
            int m   = M0 + row;
            int bb  = m & 31;
            int tt  = m >> 5;
            float4 a = *reinterpret_cast<const float4*>(
                x + ((size_t)bb * T_STEPS + tt) * 256 + k0 + kq * 4);
            As[(kq * 4 + 0) * 128 + row] = a.x;
            As[(kq * 4 + 1) * 128 + row] = a.y;
            As[(kq * 4 + 2) * 128 + row] = a.z;
            As[(kq * 4 + 3) * 128 + row] = a.w;
            int kk = f >> 5;
            int nq = f & 31;
            *reinterpret_cast<float4*>(&Bs[kk * 128 + nq * 4]) =
                *reinterpret_cast<const float4*>(W + (size_t)(k0 + kk) * 256 + jb + nq * 4);
        }
        __syncthreads();

        #pragma unroll
        for (int k = 0; k < 16; k++) {
            float a[8], bv[8];
            *reinterpret_cast<float4*>(&a[0])  = *reinterpret_cast<float4*>(&As[k * 128 + ty * 8]);
            *reinterpret_cast<float4*>(&a[4])  = *reinterpret_cast<float4*>(&As[k * 128 + ty * 8 + 4]);
            *reinterpret_cast<float4*>(&bv[0]) = *reinterpret_cast<float4*>(&Bs[k * 128 + tx * 8]);
            *reinterpret_cast<float4*>(&bv[4]) = *reinterpret_cast<float4*>(&Bs[k * 128 + tx * 8 + 4]);
            #pragma unroll
            for (int i = 0; i < 8; i++)
                #pragma unroll
                for (int j = 0; j < 8; j++)
                    acc[i][j] = fmaf(a[i], bv[j], acc[i][j]);
        }
        __syncthreads();
    }

    const float* __restrict__ bias = bg[gate];
    #pragma unroll
    for (int i = 0; i < 8; i++) {
        int m = M0 + ty * 8 + i;
        float* zr = g_Zx + (size_t)m * ZCOLS + N0 + tx * 8;
        float4 v0, v1;
        v0.x = acc[i][0] + bias[jb + tx * 8 + 0];
        v0.y = acc[i][1] + bias[jb + tx * 8 + 1];
        v0.z = acc[i][2] + bias[jb + tx * 8 + 2];
        v0.w = acc[i][3] + bias[jb + tx * 8 + 3];
        v1.x = acc[i][4] + bias[jb + tx * 8 + 4];
        v1.y = acc[i][5] + bias[jb + tx * 8 + 5];
        v1.z = acc[i][6] + bias[jb + tx * 8 + 6];
        v1.w = acc[i][7] + bias[jb + tx * 8 + 7];
        *reinterpret_cast<float4*>(zr)     = v0;
        *reinterpret_cast<float4*>(zr + 4) = v1;
    }
}

// ============================================================================
// Kernel 2: cluster recurrence, TWO software-pipelined chains (one per batch).
// 16 clusters x 8 CTAs; CTA owns 32 units x 4 gates; reg weights + FFMA2.
// Chains A (batch 0, tail=warp0, named bar 1) and B (batch 1, tail=warp4,
// named bar 2) alternate: chain A's DSMEM delivery is hidden behind chain B's
// compute and vice versa. Per-chain protocol = exact replica of proven R10.
// ============================================================================
__device__ __forceinline__ uint32_t smem_u32(const void* p) {
    uint32_t a;
    asm("{ .reg .u64 t; cvta.to.shared.u64 t, %1; cvt.u32.u64 %0, t; }"
        : "=r"(a) : "l"(p));
    return a;
}

__device__ __forceinline__ float fast_sigmoid(float z) {
    return __fdividef(1.f, 1.f + __expf(-z));
}
__device__ __forceinline__ float fast_tanh(float z) {
    return 1.f - __fdividef(2.f, __expf(2.f * z) + 1.f);
}

#define FMA2(d, a, b) \
    asm("fma.rn.f32x2 %0, %1, %2, %3;" : "=l"(d) : "l"(a), "l"(b), "l"(d))
#define ADD2(d, a, b) \
    asm("add.rn.f32x2 %0, %1, %2;" : "=l"(d) : "l"(a), "l"(b))

__device__ __forceinline__ unsigned long long pack_f2(float lo, float hi) {
    float2 f = make_float2(lo, hi);
    return *reinterpret_cast<unsigned long long*>(&f);
}
__device__ __forceinline__ float unpack_sum(unsigned long long v) {
    float2 f = *reinterpret_cast<float2*>(&v);
    return f.x + f.y;
}
__device__ __forceinline__ float2 unpack2(unsigned long long v) {
    return *reinterpret_cast<float2*>(&v);
}

// smem: 32 mbarriers (bar(src, chain, pingpong)), then floats
#define NBARS       32
#define SLICE_TX    128                  // bytes per (src, chain, boundary)
#define SW_FLOATS   (256 * 128)          // weights staging [k][gate*32+unit]
#define SH_FLOATS   (2 * 2 * 256)        // h [chain][buf][k] (st.async dest)
#define SP_FLOATS   (2 * 2 * 8 * 128)    // partials [chain][buf][ks][u*4+g]
#define SC_FLOATS   (2 * 32)             // cell state [chain][u]
#define SMEM_FLOATS (SW_FLOATS + SH_FLOATS + SP_FLOATS + SC_FLOATS)
#define SMEM_BYTES  (NBARS * 8 + SMEM_FLOATS * 4)

__global__ __launch_bounds__(REC_THREADS, 1) __cluster_dims__(CLUSTER, 1, 1)
void lstm_rec(const float* __restrict__ Wf, const float* __restrict__ Wi,
              const float* __restrict__ Wo, const float* __restrict__ Wc,
              float* __restrict__ out)
{
    extern __shared__ float smem_raw[];
    float* s_W    = smem_raw + NBARS * 2;     // [256][128] (staging)
    float* s_h    = s_W + SW_FLOATS;          // [2][2][256]
    float* s_part = s_h + SH_FLOATS;          // [2][2][8][128]
    float* s_c    = s_part + SP_FLOATS;       // [2][32]

    const int tid  = threadIdx.x;
    const int wid  = tid >> 5;
    const int lane = tid & 31;
    const int rank = blockIdx.x & (CLUSTER - 1);
    const int cid  = blockIdx.x >> 3;
    const int bb0  = cid * 2;
    const float* Wg[4] = {Wf, Wi, Wo, Wc};

    const uint32_t smem_base = smem_u32(smem_raw);
    const uint32_t sh_base = smem_base + NBARS * 8 + SW_FLOATS * 4;
    #define BAR_ADDR(src, ch, pp) \
        (smem_base + (uint32_t)((((src) * 2 + (ch)) * 2 + (pp)) * 8))

    // stage weights once: s_W[k][pc] = Wg[pc>>5][(256+k)*256 + rank*32 + (pc&31)]
    for (int idx = tid; idx < SW_FLOATS; idx += REC_THREADS) {
        int k = idx >> 7, pc = idx & 127;
        s_W[idx] = Wg[pc >> 5][(size_t)(256 + k) * 256 + rank * 32 + (pc & 31)];
    }
    for (int i = tid; i < SH_FLOATS; i += REC_THREADS) s_h[i] = 0.f;
    if (tid < 64) s_c[tid] = 0.f;

    if (tid == 0) {
        #pragma unroll
        for (int i = 0; i < NBARS; i++) {
            uint32_t b = smem_base + (uint32_t)(i * 8);
            asm volatile("mbarrier.init.shared.b64 [%0], 1;" :: "r"(b) : "memory");
            asm volatile("mbarrier.arrive.expect_tx.shared.b64 _, [%0], %1;"
                         :: "r"(b), "r"(SLICE_TX) : "memory");
        }
    }
    __syncthreads();

    // GEMV roles: warp ks = src slice [32ks, 32ks+32); lane colq = unit 0..31
    const int ks   = wid;
    const int colq = lane;

    // hoist weights (unit-major, packed over k-parity): gate c of unit colq
    unsigned long long wreg[4][16];
    #pragma unroll
    for (int c = 0; c < 4; c++)
        #pragma unroll
        for (int p = 0; p < 16; p++)
            wreg[c][p] = pack_f2(
                s_W[(ks * 32 + 2 * p)     * 128 + c * 32 + colq],
                s_W[(ks * 32 + 2 * p + 1) * 128 + c * 32 + colq]);

    asm volatile("barrier.cluster.arrive.aligned;" ::: "memory");
    asm volatile("barrier.cluster.wait.aligned;" ::: "memory");

    // tail role: warp 0 -> chain 0, warp 4 -> chain 1
    const int tailch = (wid == 0) ? 0 : ((wid == 4) ? 1 : -1);
    const int tu = lane;

    // per-warp parity state per (chain, pingpong)
    int par0[2] = {0, 0};   // pp = 0
    int par1[2] = {0, 0};   // pp = 1

    // Zx prefetch for tail threads (batch bb0 + tailch)
    float pf[4];
    if (tailch >= 0) {
        const float* z = g_Zx + ((size_t)0 * 32 + bb0 + tailch) * ZCOLS
                       + rank * 32 + tu;
        #pragma unroll
        for (int g = 0; g < 4; g++) pf[g] = __ldcg(z + g * 256);
    }

    for (int t = 0; t < T_STEPS; t++) {
        const int cbuf = t & 1, nbuf = cbuf ^ 1;

        #pragma unroll
        for (int ch = 0; ch < 2; ch++) {
            // ---- wait THIS warp's slice for chain ch, boundary t ----
            if (t >= 1) {
                const uint32_t bar = BAR_ADDR(ks, ch, cbuf);
                const int par = cbuf ? par1[ch] : par0[ch];
                uint32_t done = 0;
                do {
                    asm volatile(
                        "{\n\t.reg .pred p;\n\t"
                        "mbarrier.try_wait.parity.acquire.cta.shared::cta.b64 "
                        "p, [%1], %2, 0x989680;\n\t"
                        "selp.b32 %0, 1, 0, p;\n\t}"
                        : "=r"(done) : "r"(bar), "r"(par) : "memory");
                } while (!done);
                if (cbuf) par1[ch] ^= 1; else par0[ch] ^= 1;
                if (lane == 0 && t + 2 < T_STEPS) {
                    asm volatile("mbarrier.arrive.expect_tx.shared.b64 _, [%0], %1;"
                                 :: "r"(bar), "r"(SLICE_TX) : "memory");
                }
            }

            // ---- GEMV: 4 gates x 32 k, one batch; reg weights, FFMA2 ----
            {
                const float* hb = s_h + (ch * 2 + cbuf) * 256 + ks * 32;
                unsigned long long acc[4] = {0ull, 0ull, 0ull, 0ull};
                #pragma unroll
                for (int j = 0; j < 8; j++) {
                    ulonglong2 H = *reinterpret_cast<const ulonglong2*>(hb + j * 4);
                    #pragma unroll
                    for (int c = 0; c < 4; c++) {
                        FMA2(acc[c], wreg[c][2 * j],     H.x);
                        FMA2(acc[c], wreg[c][2 * j + 1], H.y);
                    }
                }
                float* pw = s_part + (ch * 2 + cbuf) * 1024 + ks * 128 + colq * 4;
                float4 A;
                A.x = unpack_sum(acc[0]); A.y = unpack_sum(acc[1]);
                A.z = unpack_sum(acc[2]); A.w = unpack_sum(acc[3]);
                *reinterpret_cast<float4*>(pw) = A;
            }

            // ---- chain barrier + tail ----
            if (tailch == ch) {
                asm volatile("bar.sync %0, %1;"
                             :: "r"(1 + ch), "r"(REC_THREADS) : "memory");

                // combine (8x LDS.128 + packed adds) + gates + c,h
                unsigned long long zlo = pack_f2(pf[0], pf[1]);   // (f, i)
                unsigned long long zhi = pack_f2(pf[2], pf[3]);   // (o, c)
                const float* pb = s_part + (ch * 2 + cbuf) * 1024 + tu * 4;
                #pragma unroll
                for (int q = 0; q < 8; q++) {
                    ulonglong2 v =
                        *reinterpret_cast<const ulonglong2*>(pb + q * 128);
                    ADD2(zlo, zlo, v.x);
                    ADD2(zhi, zhi, v.y);
                }
                float2 zfi = unpack2(zlo);
                float2 zoc = unpack2(zhi);
                float fg = fast_sigmoid(zfi.x);
                float ig = fast_sigmoid(zfi.y);
                float og = fast_sigmoid(zoc.x);
                float gg = fast_tanh(zoc.y);
                float cv = fmaf(fg, s_c[ch * 32 + tu], ig * gg);
                s_c[ch * 32 + tu] = cv;
                float hv = og * fast_tanh(cv);

                // push FIRST: lane-paired 8B st.async to all 8 ranks
                if (t + 1 < T_STEPS) {
                    float hp = __shfl_xor_sync(0xffffffffu, hv, 1);
                    if ((tu & 1) == 0) {
                        double val;
                        {
                            float2 f2 = make_float2(hv, hp);
                            val = *reinterpret_cast<double*>(&f2);
                        }
                        uint32_t daddr = sh_base
                            + (uint32_t)(((ch * 2 + nbuf) * 256
                                          + rank * 32 + tu) * 4);
                        uint32_t baddr = BAR_ADDR(rank, ch, nbuf);
                        #pragma unroll
                        for (int p = 0; p < CLUSTER; p++) {
                            asm volatile(
                                "{\n\t.reg .b32 ra, rb;\n\t"
                                "mapa.shared::cluster.u32 ra, %0, %2;\n\t"
                                "mapa.shared::cluster.u32 rb, %1, %2;\n\t"
                                "st.async.shared::cluster.mbarrier::complete_tx::bytes.b64 "
                                "[ra], %3, [rb];\n\t}"
                                :: "r"(daddr), "r"(baddr), "r"(p), "d"(val)
                                : "memory");
                        }
                    }
                }

                // output (fire-and-forget)
                out[((size_t)(bb0 + ch) * T_STEPS + (T_STEPS - 1 - t)) * HID
                    + rank * 32 + tu] = hv;

                // prefetch Zx(t+1)
                if (t + 1 < T_STEPS) {
                    const float* z = g_Zx
                        + ((size_t)(t + 1) * 32 + bb0 + ch) * ZCOLS
                        + rank * 32 + tu;
                    #pragma unroll
                    for (int g = 0; g < 4; g++) pf[g] = __ldcg(z + g * 256);
                }
            } else {
                // non-tail warps: non-blocking arrive, move to other chain.
                // Safe: next arrive on this bar is gated by this chain's next
                // slice wait, which transitively requires this bar's trip.
                asm volatile("bar.arrive %0, %1;"
                             :: "r"(1 + ch), "r"(REC_THREADS) : "memory");
            }
        }
    }

    // DSMEM discipline: no CTA exits while peers could still target it
    asm volatile("barrier.cluster.arrive.aligned;" ::: "memory");
    asm volatile("barrier.cluster.wait.aligned;" ::: "memory");
}

// ============================================================================
extern "C" void kernel_launch(void* const* d_in, const int* in_sizes, int n_in,
                              void* d_out, int out_size)
{
    const float* x  = (const float*)d_in[0];
    const float* Wf = (const float*)d_in[1];
    const float* bf = (const float*)d_in[2];
    const float* Wi = (const float*)d_in[3];
    const float* bi = (const float*)d_in[4];
    const float* Wo = (const float*)d_in[5];
    const float* bo = (const float*)d_in[6];
    const float* Wc = (const float*)d_in[7];
    const float* bc = (const float*)d_in[8];
    float* out = (float*)d_out;

    cudaFuncSetAttribute(lstm_rec,
                         cudaFuncAttributeMaxDynamicSharedMemorySize, SMEM_BYTES);

    dim3 g1(ZCOLS / 128, MROWS / 128);   // 8 x 512
    gemm_zx<<<g1, 256>>>(x, Wf, bf, Wi, bi, Wo, bo, Wc, bc);
    lstm_rec<<<REC_CTAS, REC_THREADS, SMEM_BYTES>>>(Wf, Wi, Wo, Wc, out);
}

// round 12
// speedup vs baseline: 1.1208x; 1.1208x over previous
#include <cuda_runtime.h>
#include <math.h>
#include <stdint.h>

#define T_STEPS 2048
#define BATCH   32
#define HID     256
#define ZCOLS   1024            // 4*HID, gate order f,i,o,c
#define MROWS   (T_STEPS * BATCH)
#define CLUSTER 8
#define REC_CTAS 128            // 16 clusters x 8 CTAs
#define REC_THREADS 256

// ---------------- scratch (device globals: no allocations allowed) ----------
__device__ float g_Zx[(size_t)MROWS * ZCOLS];   // row-major: Zx[t*32+b][col]

// ============================================================================
// Kernel 1: Zx[t*32+b][g*256+j] = sum_k x[b][t][k] * Wg[k][j] + bg[j]
// 128x128 tile SGEMM, BK=16, 256 threads, 8x8 microtile. (at fp32 roofline)
// ============================================================================
__global__ __launch_bounds__(256, 2)
void gemm_zx(const float* __restrict__ x,
             const float* __restrict__ Wf, const float* __restrict__ bf,
             const float* __restrict__ Wi, const float* __restrict__ bi,
             const float* __restrict__ Wo, const float* __restrict__ bo,
             const float* __restrict__ Wc, const float* __restrict__ bc)
{
    __shared__ float As[16 * 128];   // [k][m]
    __shared__ float Bs[16 * 128];   // [k][n]

    const int t = threadIdx.x;

    const float* Wg[4] = {Wf, Wi, Wo, Wc};
    const float* bg[4] = {bf, bi, bo, bc};

    const int N0 = blockIdx.x * 128;          // never straddles a gate
    const int gate = N0 >> 8;
    const int jb = N0 & 255;
    const float* __restrict__ W = Wg[gate];

    const int M0 = blockIdx.y * 128;
    const int tx = t & 15;
    const int ty = t >> 4;

    float acc[8][8];
    #pragma unroll
    for (int i = 0; i < 8; i++)
        #pragma unroll
        for (int j = 0; j < 8; j++) acc[i][j] = 0.f;

    for (int k0 = 0; k0 < 256; k0 += 16) {
        #pragma unroll
        for (int i = 0; i < 2; i++) {
            int f = t + i * 256;
            int kq  = f >> 7;
            int row = f & 127;
            int m   = M0 + row;
            int bb  = m & 31;
            int tt  = m >> 5;
            float4 a = *reinterpret_cast<const float4*>(
                x + ((size_t)bb * T_STEPS + tt) * 256 + k0 + kq * 4);
            As[(kq * 4 + 0) * 128 + row] = a.x;
            As[(kq * 4 + 1) * 128 + row] = a.y;
            As[(kq * 4 + 2) * 128 + row] = a.z;
            As[(kq * 4 + 3) * 128 + row] = a.w;
            int kk = f >> 5;
            int nq = f & 31;
            *reinterpret_cast<float4*>(&Bs[kk * 128 + nq * 4]) =
                *reinterpret_cast<const float4*>(W + (size_t)(k0 + kk) * 256 + jb + nq * 4);
        }
        __syncthreads();

        #pragma unroll
        for (int k = 0; k < 16; k++) {
            float a[8], bv[8];
            *reinterpret_cast<float4*>(&a[0])  = *reinterpret_cast<float4*>(&As[k * 128 + ty * 8]);
            *reinterpret_cast<float4*>(&a[4])  = *reinterpret_cast<float4*>(&As[k * 128 + ty * 8 + 4]);
            *reinterpret_cast<float4*>(&bv[0]) = *reinterpret_cast<float4*>(&Bs[k * 128 + tx * 8]);
            *reinterpret_cast<float4*>(&bv[4]) = *reinterpret_cast<float4*>(&Bs[k * 128 + tx * 8 + 4]);
            #pragma unroll
            for (int i = 0; i < 8; i++)
                #pragma unroll
                for (int j = 0; j < 8; j++)
                    acc[i][j] = fmaf(a[i], bv[j], acc[i][j]);
        }
        __syncthreads();
    }

    const float* __restrict__ bias = bg[gate];
    #pragma unroll
    for (int i = 0; i < 8; i++) {
        int m = M0 + ty * 8 + i;
        float* zr = g_Zx + (size_t)m * ZCOLS + N0 + tx * 8;
        float4 v0, v1;
        v0.x = acc[i][0] + bias[jb + tx * 8 + 0];
        v0.y = acc[i][1] + bias[jb + tx * 8 + 1];
        v0.z = acc[i][2] + bias[jb + tx * 8 + 2];
        v0.w = acc[i][3] + bias[jb + tx * 8 + 3];
        v1.x = acc[i][4] + bias[jb + tx * 8 + 4];
        v1.y = acc[i][5] + bias[jb + tx * 8 + 5];
        v1.z = acc[i][6] + bias[jb + tx * 8 + 6];
        v1.w = acc[i][7] + bias[jb + tx * 8 + 7];
        *reinterpret_cast<float4*>(zr)     = v0;
        *reinterpret_cast<float4*>(zr + 4) = v1;
    }
}

// ============================================================================
// Kernel 2: cluster recurrence (R10 skeleton). Register weights + FFMA2,
// per-source slice mbarriers, st.async exchange. Changes vs R10:
//  - ALL warps bar.sync (fixes latent double-arrival race of bar.arrive)
//  - tail spread over warps 0-3 (16 lanes each) -> one tail slice per SMSP
// ============================================================================
__device__ __forceinline__ uint32_t smem_u32(const void* p) {
    uint32_t a;
    asm("{ .reg .u64 t; cvta.to.shared.u64 t, %1; cvt.u32.u64 %0, t; }"
        : "=r"(a) : "l"(p));
    return a;
}

__device__ __forceinline__ float fast_sigmoid(float z) {
    return __fdividef(1.f, 1.f + __expf(-z));
}
__device__ __forceinline__ float fast_tanh(float z) {
    return 1.f - __fdividef(2.f, __expf(2.f * z) + 1.f);
}

#define FMA2(d, a, b) \
    asm("fma.rn.f32x2 %0, %1, %2, %3;" : "=l"(d) : "l"(a), "l"(b), "l"(d))
#define ADD2(d, a, b) \
    asm("add.rn.f32x2 %0, %1, %2;" : "=l"(d) : "l"(a), "l"(b))

__device__ __forceinline__ unsigned long long pack_f2(float lo, float hi) {
    float2 f = make_float2(lo, hi);
    return *reinterpret_cast<unsigned long long*>(&f);
}
__device__ __forceinline__ float unpack_sum(unsigned long long v) {
    float2 f = *reinterpret_cast<float2*>(&v);
    return f.x + f.y;
}
__device__ __forceinline__ float2 unpack2(unsigned long long v) {
    return *reinterpret_cast<float2*>(&v);
}

// smem layout: 16 mbarriers (128B), then floats
#define NBARS       16                   // 8 src x 2 (ping-pong)
#define SLICE_TX    256                  // bytes per (src, boundary)
#define SW_FLOATS   (256 * 128)          // weights [k][gate*32+unit] (staging)
#define SH_FLOATS   (2 * 2 * 256)        // h [buf][b][k]  (st.async dest)
#define SP_FLOATS   (8 * 2 * 128)        // partials [ks][b][unit*4+gate], x2
#define SC_FLOATS   (2 * 32)             // cell state [b][u]
#define SMEM_FLOATS (SW_FLOATS + SH_FLOATS + 2 * SP_FLOATS + SC_FLOATS)
#define SMEM_BYTES  (NBARS * 8 + SMEM_FLOATS * 4)

__global__ __launch_bounds__(REC_THREADS, 1) __cluster_dims__(CLUSTER, 1, 1)
void lstm_rec(const float* __restrict__ Wf, const float* __restrict__ Wi,
              const float* __restrict__ Wo, const float* __restrict__ Wc,
              float* __restrict__ out)
{
    extern __shared__ float smem_raw[];
    float* s_W    = smem_raw + NBARS * 2;     // [256][128] (staging)
    float* s_h    = s_W + SW_FLOATS;          // [2][2][256]
    float* s_part = s_h + SH_FLOATS;          // [2][8][2][32 units][4 gates]
    float* s_c    = s_part + 2 * SP_FLOATS;   // [2][32]

    const int tid  = threadIdx.x;
    const int wid  = tid >> 5;
    const int lane = tid & 31;
    const int rank = blockIdx.x & (CLUSTER - 1);
    const int cid  = blockIdx.x >> 3;
    const int bb0  = cid * 2;
    const float* Wg[4] = {Wf, Wi, Wo, Wc};

    const uint32_t smem_base = smem_u32(smem_raw);
    const uint32_t sh_base = smem_base + NBARS * 8 + SW_FLOATS * 4;
    #define BAR_ADDR(src, pp) (smem_base + (uint32_t)(((src) * 2 + (pp)) * 8))

    // stage weights once: s_W[k][pc] = Wg[pc>>5][(256+k)*256 + rank*32 + (pc&31)]
    for (int idx = tid; idx < SW_FLOATS; idx += REC_THREADS) {
        int k = idx >> 7, pc = idx & 127;
        s_W[idx] = Wg[pc >> 5][(size_t)(256 + k) * 256 + rank * 32 + (pc & 31)];
    }
    for (int i = tid; i < SH_FLOATS; i += REC_THREADS) s_h[i] = 0.f;
    if (tid < 64) s_c[tid] = 0.f;

    if (tid == 0) {
        #pragma unroll
        for (int i = 0; i < NBARS; i++) {
            uint32_t b = smem_base + (uint32_t)(i * 8);
            asm volatile("mbarrier.init.shared.b64 [%0], 1;" :: "r"(b) : "memory");
            asm volatile("mbarrier.arrive.expect_tx.shared.b64 _, [%0], %1;"
                         :: "r"(b), "r"(SLICE_TX) : "memory");
        }
    }
    __syncthreads();

    // GEMV roles: warp ks (32 k's = src ks's slice), lane colq = UNIT 0..31
    const int ks   = wid;
    const int colq = lane;

    // hoist 128 weights to regs, packed over k-parity; gate c of unit colq
    unsigned long long wreg[4][16];
    #pragma unroll
    for (int c = 0; c < 4; c++)
        #pragma unroll
        for (int p = 0; p < 16; p++)
            wreg[c][p] = pack_f2(
                s_W[(ks * 32 + 2 * p)     * 128 + c * 32 + colq],
                s_W[(ks * 32 + 2 * p + 1) * 128 + c * 32 + colq]);

    asm volatile("barrier.cluster.arrive.aligned;" ::: "memory");
    asm volatile("barrier.cluster.wait.aligned;" ::: "memory");

    // tail roles: warps 0-3, lanes 0-15. One tail slice per SMSP.
    const bool is_tail = (wid < 4) && (lane < 16);
    const int tb = wid >> 1;                         // batch 0/1
    const int tu = ((wid & 1) << 4) | (lane & 15);   // unit 0..31

    // per-warp parity state (slice barrier ping-pong)
    int par0 = 0, par1 = 0;

    // Zx prefetch (tail threads): gates f,i,o,c for (tb, tu)
    float pf[4];
    if (is_tail) {
        const float* z = g_Zx + ((size_t)0 * 32 + bb0 + tb) * ZCOLS + rank * 32 + tu;
        #pragma unroll
        for (int g = 0; g < 4; g++) pf[g] = __ldcg(z + g * 256);
    }

    for (int t = 0; t < T_STEPS; t++) {
        const int cbuf = t & 1, nbuf = cbuf ^ 1;

        // wait for THIS warp's slice (boundary t), t >= 1
        if (t >= 1) {
            const uint32_t bar = BAR_ADDR(ks, cbuf);
            const int par = cbuf ? par1 : par0;
            uint32_t done = 0;
            do {
                asm volatile(
                    "{\n\t.reg .pred p;\n\t"
                    "mbarrier.try_wait.parity.acquire.cta.shared::cta.b64 "
                    "p, [%1], %2, 0x989680;\n\t"
                    "selp.b32 %0, 1, 0, p;\n\t}"
                    : "=r"(done) : "r"(bar), "r"(par) : "memory");
            } while (!done);
            if (cbuf) par1 ^= 1; else par0 ^= 1;
            if (lane == 0 && t + 2 < T_STEPS) {
                asm volatile("mbarrier.arrive.expect_tx.shared.b64 _, [%0], %1;"
                             :: "r"(bar), "r"(SLICE_TX) : "memory");
            }
        }

        // GEMV: 4 gates x 2 batches x 32 k; reg weights, FFMA2
        {
            const float* hb0 = s_h + (cbuf * 2) * 256 + ks * 32;
            const float* hb1 = hb0 + 256;
            unsigned long long acc[4][2];
            #pragma unroll
            for (int c = 0; c < 4; c++) { acc[c][0] = 0ull; acc[c][1] = 0ull; }

            #pragma unroll
            for (int j = 0; j < 8; j++) {
                ulonglong2 H0 = *reinterpret_cast<const ulonglong2*>(hb0 + j * 4);
                ulonglong2 H1 = *reinterpret_cast<const ulonglong2*>(hb1 + j * 4);
                #pragma unroll
                for (int c = 0; c < 4; c++) {
                    FMA2(acc[c][0], wreg[c][2 * j],     H0.x);
                    FMA2(acc[c][0], wreg[c][2 * j + 1], H0.y);
                    FMA2(acc[c][1], wreg[c][2 * j],     H1.x);
                    FMA2(acc[c][1], wreg[c][2 * j + 1], H1.y);
                }
            }
            // unit-major store: float4 = (f,i,o,c) partials of unit colq
            float* pw = s_part + cbuf * SP_FLOATS + (ks * 2) * 128 + colq * 4;
            float4 A0, A1;
            A0.x = unpack_sum(acc[0][0]); A0.y = unpack_sum(acc[1][0]);
            A0.z = unpack_sum(acc[2][0]); A0.w = unpack_sum(acc[3][0]);
            A1.x = unpack_sum(acc[0][1]); A1.y = unpack_sum(acc[1][1]);
            A1.z = unpack_sum(acc[2][1]); A1.w = unpack_sum(acc[3][1]);
            *reinterpret_cast<float4*>(pw)       = A0;
            *reinterpret_cast<float4*>(pw + 128) = A1;
        }

        // full blocking barrier (every warp, every phase exactly once)
        asm volatile("bar.sync 1, %0;" :: "r"(REC_THREADS) : "memory");

        // fused tail: warps 0-3, lanes 0-15 (one quarter per SMSP)
        if (is_tail) {
            unsigned long long zlo = pack_f2(pf[0], pf[1]);   // (f, i)
            unsigned long long zhi = pack_f2(pf[2], pf[3]);   // (o, c)
            const float* pb = s_part + cbuf * SP_FLOATS + tb * 128 + tu * 4;
            #pragma unroll
            for (int q = 0; q < 8; q++) {
                ulonglong2 v = *reinterpret_cast<const ulonglong2*>(pb + q * 256);
                ADD2(zlo, zlo, v.x);
                ADD2(zhi, zhi, v.y);
            }
            float2 zfi = unpack2(zlo);
            float2 zoc = unpack2(zhi);
            float fg = fast_sigmoid(zfi.x);
            float ig = fast_sigmoid(zfi.y);
            float og = fast_sigmoid(zoc.x);
            float gg = fast_tanh(zoc.y);
            float cv = fmaf(fg, s_c[tb * 32 + tu], ig * gg);
            s_c[tb * 32 + tu] = cv;
            float hv = og * fast_tanh(cv);

            // push FIRST (unblocks peers): lane-paired 8B st.async to 8 ranks
            if (t + 1 < T_STEPS) {
                float hp = __shfl_xor_sync(0x0000ffffu, hv, 1);
                if ((tu & 1) == 0) {
                    double val;
                    {
                        float2 f2 = make_float2(hv, hp);
                        val = *reinterpret_cast<double*>(&f2);
                    }
                    uint32_t daddr = sh_base
                        + (uint32_t)(((nbuf * 2 + tb) * 256 + rank * 32 + tu) * 4);
                    uint32_t baddr = BAR_ADDR(rank, nbuf);
                    #pragma unroll
                    for (int p = 0; p < CLUSTER; p++) {
                        asm volatile(
                            "{\n\t.reg .b32 ra, rb;\n\t"
                            "mapa.shared::cluster.u32 ra, %0, %2;\n\t"
                            "mapa.shared::cluster.u32 rb, %1, %2;\n\t"
                            "st.async.shared::cluster.mbarrier::complete_tx::bytes.b64 "
                            "[ra], %3, [rb];\n\t}"
                            :: "r"(daddr), "r"(baddr), "r"(p), "d"(val) : "memory");
                    }
                }
            }

            // output (fire-and-forget)
            out[((size_t)(bb0 + tb) * T_STEPS + (T_STEPS - 1 - t)) * HID
                + rank * 32 + tu] = hv;

            // prefetch Zx(t+1)
            if (t + 1 < T_STEPS) {
                const float* z = g_Zx + ((size_t)(t + 1) * 32 + bb0 + tb) * ZCOLS
                               + rank * 32 + tu;
                #pragma unroll
                for (int g = 0; g < 4; g++) pf[g] = __ldcg(z + g * 256);
            }
        }
        // s_part double-buffered; s_h ping-pong: t+2 overwrites are
        // transitively ordered after this CTA's tail of step t (via the
        // exchange dependency chain), so no second barrier is needed.
    }

    // DSMEM discipline: no CTA exits while peers could still target it
    asm volatile("barrier.cluster.arrive.aligned;" ::: "memory");
    asm volatile("barrier.cluster.wait.aligned;" ::: "memory");
}

// ============================================================================
extern "C" void kernel_launch(void* const* d_in, const int* in_sizes, int n_in,
                              void* d_out, int out_size)
{
    const float* x  = (const float*)d_in[0];
    const float* Wf = (const float*)d_in[1];
    const float* bf = (const float*)d_in[2];
    const float* Wi = (const float*)d_in[3];
    const float* bi = (const float*)d_in[4];
    const float* Wo = (const float*)d_in[5];
    const float* bo = (const float*)d_in[6];
    const float* Wc = (const float*)d_in[7];
    const float* bc = (const float*)d_in[8];
    float* out = (float*)d_out;

    cudaFuncSetAttribute(lstm_rec,
                         cudaFuncAttributeMaxDynamicSharedMemorySize, SMEM_BYTES);

    dim3 g1(ZCOLS / 128, MROWS / 128);   // 8 x 512
    gemm_zx<<<g1, 256>>>(x, Wf, bf, Wi, bi, Wo, bo, Wc, bc);
    lstm_rec<<<REC_CTAS, REC_THREADS, SMEM_BYTES>>>(Wf, Wi, Wo, Wc, out);
}